// round 13
// baseline (speedup 1.0000x reference)
#include <cuda_runtime.h>
#include <cuda_fp16.h>
#include <math.h>
#include <stdint.h>

#define SEQ   4096
#define HID   2048
#define NH    16
#define NKV   8
#define HD    128

// ---------------- scratch ----------------
__device__ __half g_HS16[SEQ * HID];
__device__ __half g_WQ16[NH  * HD * HID];
__device__ __half g_WK16[NKV * HD * HID];
__device__ __half g_WV16[NKV * HD * HID];
__device__ __half g_WO16[HID * NH * HD];
__device__ __half g_Q16 [SEQ * NH  * HD];
__device__ __half g_K16 [SEQ * NKV * HD];
__device__ __half g_VT16[NKV * HD * SEQ];
__device__ __half g_AO16[SEQ * NH  * HD];

#define QSCALE (0.08838834764831845f * 1.4426950408889634f)

// ---------------- PTX helpers ----------------
__device__ __forceinline__ void mma_f16(float& d0, float& d1, float& d2, float& d3,
                                        uint32_t a0, uint32_t a1, uint32_t a2, uint32_t a3,
                                        uint32_t b0, uint32_t b1)
{
    asm volatile(
        "mma.sync.aligned.m16n8k16.row.col.f32.f16.f16.f32 "
        "{%0,%1,%2,%3},{%4,%5,%6,%7},{%8,%9},{%0,%1,%2,%3};\n"
        : "+f"(d0), "+f"(d1), "+f"(d2), "+f"(d3)
        : "r"(a0), "r"(a1), "r"(a2), "r"(a3), "r"(b0), "r"(b1));
}
__device__ __forceinline__ void ldsm_x4(uint32_t& r0, uint32_t& r1,
                                        uint32_t& r2, uint32_t& r3, uint32_t addr)
{
    asm volatile("ldmatrix.sync.aligned.m8n8.x4.shared.b16 {%0,%1,%2,%3}, [%4];"
                 : "=r"(r0), "=r"(r1), "=r"(r2), "=r"(r3) : "r"(addr));
}
__device__ __forceinline__ uint32_t smem_u32(const void* p)
{
    return (uint32_t)__cvta_generic_to_shared(p);
}
__device__ __forceinline__ float ex2f(float x)
{
    float r;
    asm("ex2.approx.ftz.f32 %0, %1;" : "=f"(r) : "f"(x));
    return r;
}
__device__ __forceinline__ uint32_t packh2(float lo, float hi)
{
    __half2 h = __floats2half2_rn(lo, hi);
    return *(uint32_t*)&h;
}
__device__ __forceinline__ void cp_async16(void* smem, const void* gmem)
{
    uint32_t s = smem_u32(smem);
    asm volatile("cp.async.cg.shared.global [%0], [%1], 16;\n" :: "r"(s), "l"(gmem));
}
#define CP_COMMIT()  asm volatile("cp.async.commit_group;\n")
#define CP_WAIT(n)   asm volatile("cp.async.wait_group %0;\n" :: "n"(n))

// =================================================================
// batched fp32 -> fp16 convert (5 arrays, one launch)
// =================================================================
__global__ __launch_bounds__(256) void cvt_h5(
    const float4* s0, __half2* d0, int n0,
    const float4* s1, __half2* d1, int n1,
    const float4* s2, __half2* d2, int n2,
    const float4* s3, __half2* d3, int n3,
    const float4* s4, __half2* d4, int n4)
{
    const float4* src; __half2* dst; int n;
    switch (blockIdx.y) {
        case 0: src = s0; dst = d0; n = n0; break;
        case 1: src = s1; dst = d1; n = n1; break;
        case 2: src = s2; dst = d2; n = n2; break;
        case 3: src = s3; dst = d3; n = n3; break;
        default: src = s4; dst = d4; n = n4; break;
    }
    int i = blockIdx.x * blockDim.x + threadIdx.x;
    if (i < n) {
        float4 v = src[i];
        dst[2 * i]     = __floats2half2_rn(v.x, v.y);
        dst[2 * i + 1] = __floats2half2_rn(v.z, v.w);
    }
}

// =================================================================
// GEMM core (R11 config, best measured): CTA 128x128, 256 threads,
// 8 warps 4x2, warp tile 32x64, BK=32, 3-stage cp.async, 1 barrier/ktile.
// C[M,N] = A[M,K]*B[N,K]^T.
// mode 0: fp32 C; mode 1: fp16 C; mode 2: fused RMSNorm+RoPE -> fp16.
// =================================================================
#define TAS3 40                        // halves per smem row (32+8)
#define STG3 (2 * 128 * TAS3)          // 10240 halves per stage (A+B)
#define GEMM3_SMEM 73728
#define XS 132                         // fp32 stride of norm exchange buffer

__device__ __forceinline__ void gemm_core(
    const __half* __restrict__ A, const __half* __restrict__ B,
    void* __restrict__ Cv, int N, int K, int mode,
    const float* __restrict__ nw, const float* __restrict__ cosv,
    const float* __restrict__ sinv, float outscale,
    int m0, int n0, __half* sh)
{
    const int tid  = threadIdx.x;
    const int w    = tid >> 5, lane = tid & 31;
    const int wm   = w >> 1,   wn   = w & 1;
    const int q    = lane >> 2, t = lane & 3;

    const uint32_t a_loff = (uint32_t)(((wm * 32 + (lane & 15)) * TAS3 + (lane >> 4) * 8) * 2);
    const uint32_t b_loff = (uint32_t)(((wn * 64 + ((lane >> 4) & 1) * 8 + (lane & 7)) * TAS3) * 2
                                       + ((lane >> 3) & 1) * 16);

    float acc[2][8][4];
#pragma unroll
    for (int mt = 0; mt < 2; mt++)
#pragma unroll
        for (int nt = 0; nt < 8; nt++)
#pragma unroll
            for (int c = 0; c < 4; c++) acc[mt][nt][c] = 0.0f;

    const int T = K / 32;

    auto load_stage = [&](int k0, int st) {
        __half* as = sh + st * STG3;
        __half* bs = as + 128 * TAS3;
#pragma unroll
        for (int it = 0; it < 2; it++) {
            int li  = tid + it * 256;
            int row = li >> 2;
            int c   = (li & 3) * 8;
            cp_async16(as + row * TAS3 + c, A + (size_t)(m0 + row) * K + k0 + c);
            cp_async16(bs + row * TAS3 + c, B + (size_t)(n0 + row) * K + k0 + c);
        }
        CP_COMMIT();
    };

    load_stage(0, 0);
    load_stage(32, 1);

    for (int ti = 0; ti < T; ti++) {
        if (ti == 0) { CP_WAIT(1); }
        __syncthreads();
        if (ti + 2 < T)      { load_stage((ti + 2) * 32, (ti + 2) % 3); CP_WAIT(1); }
        else if (ti + 1 < T) { CP_WAIT(0); }

        const uint32_t as_u = smem_u32(sh + (ti % 3) * STG3);
        const uint32_t bs_u = as_u + 128 * TAS3 * 2;

#pragma unroll
        for (int ks = 0; ks < 2; ks++) {
            const uint32_t kb = ks * 32;
            uint32_t af[2][4], bf[8][2];
            ldsm_x4(af[0][0], af[0][1], af[0][2], af[0][3], as_u + a_loff + kb);
            ldsm_x4(af[1][0], af[1][1], af[1][2], af[1][3],
                    as_u + a_loff + 16 * TAS3 * 2 + kb);
#pragma unroll
            for (int p = 0; p < 4; p++)
                ldsm_x4(bf[2 * p][0], bf[2 * p][1], bf[2 * p + 1][0], bf[2 * p + 1][1],
                        bs_u + b_loff + p * 16 * TAS3 * 2 + kb);
#pragma unroll
            for (int mt = 0; mt < 2; mt++)
#pragma unroll
                for (int nt = 0; nt < 8; nt++)
                    mma_f16(acc[mt][nt][0], acc[mt][nt][1], acc[mt][nt][2], acc[mt][nt][3],
                            af[mt][0], af[mt][1], af[mt][2], af[mt][3],
                            bf[nt][0], bf[nt][1]);
        }
    }

    if (mode == 0) {
        float* C = (float*)Cv;
#pragma unroll
        for (int mt = 0; mt < 2; mt++) {
            const int row = m0 + wm * 32 + mt * 16 + q;
#pragma unroll
            for (int nt = 0; nt < 8; nt++) {
                const int col = n0 + wn * 64 + nt * 8 + 2 * t;
                *(float2*)(C + (size_t)row * N + col)       = make_float2(acc[mt][nt][0], acc[mt][nt][1]);
                *(float2*)(C + (size_t)(row + 8) * N + col) = make_float2(acc[mt][nt][2], acc[mt][nt][3]);
            }
        }
    } else if (mode == 1) {
        __half* C = (__half*)Cv;
#pragma unroll
        for (int mt = 0; mt < 2; mt++) {
            const int row = m0 + wm * 32 + mt * 16 + q;
#pragma unroll
            for (int nt = 0; nt < 8; nt++) {
                const int col = n0 + wn * 64 + nt * 8 + 2 * t;
                *(uint32_t*)(C + (size_t)row * N + col)       = packh2(acc[mt][nt][0], acc[mt][nt][1]);
                *(uint32_t*)(C + (size_t)(row + 8) * N + col) = packh2(acc[mt][nt][2], acc[mt][nt][3]);
            }
        }
    } else {
        // ---- fused RMSNorm + RoPE epilogue (TBN == HD; partner = col^64) ----
        __syncthreads();
        float* red  = (float*)sh;          // [128][2]
        float* xbuf = (float*)sh + 256;    // [128][132]

#pragma unroll
        for (int mt = 0; mt < 2; mt++)
#pragma unroll
            for (int hf = 0; hf < 2; hf++) {
                float ss = 0.0f;
#pragma unroll
                for (int nt = 0; nt < 8; nt++) {
                    float a0 = acc[mt][nt][hf * 2], a1 = acc[mt][nt][hf * 2 + 1];
                    ss += a0 * a0 + a1 * a1;
                }
                ss += __shfl_xor_sync(0xffffffffu, ss, 1);
                ss += __shfl_xor_sync(0xffffffffu, ss, 2);
                if (t == 0) red[(wm * 32 + mt * 16 + q + hf * 8) * 2 + wn] = ss;
            }
        __syncthreads();

#pragma unroll
        for (int mt = 0; mt < 2; mt++)
#pragma unroll
            for (int hf = 0; hf < 2; hf++) {
                const int row = wm * 32 + mt * 16 + q + hf * 8;
                const float tot = red[row * 2] + red[row * 2 + 1];
                const float rms = rsqrtf(tot * (1.0f / HD) + 1e-6f);
#pragma unroll
                for (int nt = 0; nt < 8; nt++) {
                    const int col = wn * 64 + nt * 8 + 2 * t;
                    xbuf[row * XS + col]     = acc[mt][nt][hf * 2]     * rms * nw[col];
                    xbuf[row * XS + col + 1] = acc[mt][nt][hf * 2 + 1] * rms * nw[col + 1];
                }
            }
        __syncthreads();

        __half* C = (__half*)Cv;
        const float sgn = (wn == 0) ? -1.0f : 1.0f;
#pragma unroll
        for (int mt = 0; mt < 2; mt++)
#pragma unroll
            for (int hf = 0; hf < 2; hf++) {
                const int row = wm * 32 + mt * 16 + q + hf * 8;
                const int s   = m0 + row;
                __half* Orow  = C + (size_t)s * N + n0;
#pragma unroll
                for (int nt = 0; nt < 8; nt++) {
                    const int col = wn * 64 + nt * 8 + 2 * t;
                    float x0 = xbuf[row * XS + col];
                    float x1 = xbuf[row * XS + col + 1];
                    float p0 = xbuf[row * XS + (col ^ 64)];
                    float p1 = xbuf[row * XS + (col ^ 64) + 1];
                    float2 cs = *(const float2*)(cosv + (size_t)s * HD + col);
                    float2 sn = *(const float2*)(sinv + (size_t)s * HD + col);
                    float r0 = (x0 * cs.x + sgn * p0 * sn.x) * outscale;
                    float r1 = (x1 * cs.y + sgn * p1 * sn.y) * outscale;
                    *(uint32_t*)(Orow + col) = packh2(r0, r1);
                }
            }
    }
}

// fused Q+K+V projection launch: 1024 CTAs, range-decoded.
__global__ __launch_bounds__(256, 2) void qkv_fused(
    const __half* __restrict__ HS, const __half* __restrict__ WQ,
    const __half* __restrict__ WK, const __half* __restrict__ WV,
    __half* __restrict__ Q16, __half* __restrict__ K16, __half* __restrict__ VT,
    const float* __restrict__ qw, const float* __restrict__ kw,
    const float* __restrict__ cosv, const float* __restrict__ sinv)
{
    extern __shared__ __half sh[];
    const int bid = blockIdx.x;
    const __half *A, *B; void* C; int N, mode, m0, n0;
    const float* nwp = nullptr; float osc = 0.0f;
    if (bid < 512) {            // Q: M=4096, N=2048 -> 32 x 16 tiles
        A = HS; B = WQ; C = Q16; N = 2048; mode = 2; nwp = qw; osc = QSCALE;
        n0 = (bid & 15) * 128; m0 = (bid >> 4) * 128;
    } else if (bid < 768) {     // K: M=4096, N=1024 -> 32 x 8
        int r = bid - 512;
        A = HS; B = WK; C = K16; N = 1024; mode = 2; nwp = kw; osc = 1.0f;
        n0 = (r & 7) * 128; m0 = (r >> 3) * 128;
    } else {                    // V^T: M=1024, N=4096 -> 8 x 32
        int r = bid - 768;
        A = WV; B = HS; C = VT; N = 4096; mode = 1;
        n0 = (r & 31) * 128; m0 = (r >> 5) * 128;
    }
    gemm_core(A, B, C, N, HID, mode, nwp, cosv, sinv, osc, m0, n0, sh);
}

// single-GEMM launch (wo projection)
__global__ __launch_bounds__(256, 2) void gemm_one(
    const __half* __restrict__ A, const __half* __restrict__ B,
    void* __restrict__ Cv, int N, int K, int mode)
{
    extern __shared__ __half sh[];
    gemm_core(A, B, Cv, N, K, mode, nullptr, nullptr, nullptr, 0.0f,
              blockIdx.y * 128, blockIdx.x * 128, sh);
}

// =================================================================
// Causal flash attention — 3-stage cp.async pipeline, ONE barrier/tile.
// =================================================================
#define FQ   128
#define FK   64
#define KSTR 136
#define VTSTR 72
#define QSTR 136
#define KVSTG (FK * KSTR + FQ * VTSTR)     // 17920 halves / stage
#define FLASH_SMEM (3 * KVSTG * 2)         // 107520 B

__global__ __launch_bounds__(256, 2) void flash_h(const __half* __restrict__ Q,
                                                  const __half* __restrict__ K,
                                                  const __half* __restrict__ VT,
                                                  __half* __restrict__ O)
{
    extern __shared__ __half sh[];

    const int tid  = threadIdx.x;
    const int w    = tid >> 5, lane = tid & 31;
    const int q    = lane >> 2, t = lane & 3;
    const int h    = blockIdx.y;
    const int q0   = ((int)gridDim.x - 1 - (int)blockIdx.x) * FQ;
    const int kvh  = h >> 1;
    const int r0   = w * 16;

    const __half* Qb  = Q  + (size_t)h * HD;
    const __half* Kb  = K  + (size_t)kvh * HD;
    const __half* VTb = VT + (size_t)(kvh * HD) * SEQ;

    const uint32_t k_loff = (uint32_t)(((((lane >> 4) & 1) * 8 + (lane & 7)) * KSTR) * 2
                                       + ((lane >> 3) & 1) * 16);
    const uint32_t v_loff = (uint32_t)(((((lane >> 4) & 1) * 8 + (lane & 7)) * VTSTR) * 2
                                       + ((lane >> 3) & 1) * 16);

    // ---- stage Q in stage0 area, extract fragments, then free the area ----
    uint32_t qf[8][4];
    {
        __half* Qs = sh;
#pragma unroll
        for (int it = 0; it < 8; it++) {
            int li = tid + it * 256;
            int r  = li >> 4;
            int c  = (li & 15) * 8;
            *(float4*)(Qs + r * QSTR + c) =
                *(const float4*)(Qb + (size_t)(q0 + r) * (NH * HD) + c);
        }
        __syncthreads();
        const uint32_t qs_u = smem_u32(Qs);
        const uint32_t q_loff = (uint32_t)(((r0 + (lane & 15)) * QSTR + (lane >> 4) * 8) * 2);
#pragma unroll
        for (int ks = 0; ks < 8; ks++)
            ldsm_x4(qf[ks][0], qf[ks][1], qf[ks][2], qf[ks][3], qs_u + q_loff + ks * 32);
        __syncthreads();
    }

    float o[16][4];
    float m_i[2], l_i[2];
#pragma unroll
    for (int hf = 0; hf < 2; hf++) { m_i[hf] = -1e30f; l_i[hf] = 0.0f; }
#pragma unroll
    for (int nt = 0; nt < 16; nt++)
#pragma unroll
        for (int c = 0; c < 4; c++) o[nt][c] = 0.0f;

    const int ktiles = q0 / FK + 2;

    auto prefetch = [&](int kt, int st) {
        __half* Ks = sh + st * KVSTG;
        __half* Vs = Ks + FK * KSTR;
        const int k0 = kt * FK;
#pragma unroll
        for (int it = 0; it < 4; it++) {
            int li = tid + it * 256;
            int r  = li >> 4;
            int c  = (li & 15) * 8;
            cp_async16(Ks + r * KSTR + c, Kb + (size_t)(k0 + r) * (NKV * HD) + c);
        }
#pragma unroll
        for (int it = 0; it < 4; it++) {
            int li = tid + it * 256;
            int r  = li >> 3;
            int c  = (li & 7) * 8;
            cp_async16(Vs + r * VTSTR + c, VTb + (size_t)r * SEQ + k0 + c);
        }
        CP_COMMIT();
    };

    prefetch(0, 0);
    prefetch(1, 1);

    for (int kt = 0; kt < ktiles; kt++) {
        const int k0 = kt * FK;

        if (kt == 0) { CP_WAIT(1); }
        __syncthreads();
        if (kt + 2 < ktiles)      { prefetch(kt + 2, (kt + 2) % 3); CP_WAIT(1); }
        else if (kt + 1 < ktiles) { CP_WAIT(0); }

        const uint32_t ks_u = smem_u32(sh + (kt % 3) * KVSTG);
        const uint32_t vs_u = ks_u + FK * KSTR * 2;

        // ---- S = Q K^T ----
        float s[8][4];
#pragma unroll
        for (int nt = 0; nt < 8; nt++)
#pragma unroll
            for (int c = 0; c < 4; c++) s[nt][c] = 0.0f;

#pragma unroll
        for (int ks = 0; ks < 8; ks++) {
            const uint32_t kb = ks * 32;
            uint32_t bf[8][2];
#pragma unroll
            for (int p = 0; p < 4; p++)
                ldsm_x4(bf[2 * p][0], bf[2 * p][1], bf[2 * p + 1][0], bf[2 * p + 1][1],
                        ks_u + k_loff + p * 16 * KSTR * 2 + kb);
#pragma unroll
            for (int nt = 0; nt < 8; nt++)
                mma_f16(s[nt][0], s[nt][1], s[nt][2], s[nt][3],
                        qf[ks][0], qf[ks][1], qf[ks][2], qf[ks][3],
                        bf[nt][0], bf[nt][1]);
        }

        // ---- causal mask (last two tiles only) ----
        if (k0 + FK - 1 > q0) {
#pragma unroll
            for (int hf = 0; hf < 2; hf++) {
                const int row = q0 + r0 + q + hf * 8;
#pragma unroll
                for (int nt = 0; nt < 8; nt++) {
                    const int col = k0 + nt * 8 + 2 * t;
                    if (col     > row) s[nt][hf * 2]     = -1e30f;
                    if (col + 1 > row) s[nt][hf * 2 + 1] = -1e30f;
                }
            }
        }

        // ---- online softmax (exp2 domain) ----
#pragma unroll
        for (int hf = 0; hf < 2; hf++) {
            float rm = -1e30f;
#pragma unroll
            for (int nt = 0; nt < 8; nt++)
                rm = fmaxf(rm, fmaxf(s[nt][hf * 2], s[nt][hf * 2 + 1]));
            rm = fmaxf(rm, __shfl_xor_sync(0xffffffffu, rm, 1));
            rm = fmaxf(rm, __shfl_xor_sync(0xffffffffu, rm, 2));

            const float mnew  = fmaxf(m_i[hf], rm);
            const float alpha = ex2f(m_i[hf] - mnew);
            float rs = 0.0f;
#pragma unroll
            for (int nt = 0; nt < 8; nt++) {
                float p0 = ex2f(s[nt][hf * 2]     - mnew);
                float p1 = ex2f(s[nt][hf * 2 + 1] - mnew);
                rs += p0 + p1;
                s[nt][hf * 2]     = p0;
                s[nt][hf * 2 + 1] = p1;
            }
            rs += __shfl_xor_sync(0xffffffffu, rs, 1);
            rs += __shfl_xor_sync(0xffffffffu, rs, 2);

            l_i[hf] = l_i[hf] * alpha + rs;
            m_i[hf] = mnew;

            if (__any_sync(0xffffffffu, alpha != 1.0f)) {
#pragma unroll
                for (int nt = 0; nt < 16; nt++) {
                    o[nt][hf * 2]     *= alpha;
                    o[nt][hf * 2 + 1] *= alpha;
                }
            }
        }

        // ---- pack P -> fp16 A-fragments (register only) ----
        uint32_t paf[4][4];
#pragma unroll
        for (int j = 0; j < 4; j++) {
            paf[j][0] = packh2(s[2 * j][0],     s[2 * j][1]);
            paf[j][1] = packh2(s[2 * j][2],     s[2 * j][3]);
            paf[j][2] = packh2(s[2 * j + 1][0], s[2 * j + 1][1]);
            paf[j][3] = packh2(s[2 * j + 1][2], s[2 * j + 1][3]);
        }

        // ---- O += P V (Vt [d][key]) ----
#pragma unroll
        for (int j = 0; j < 4; j++) {
            const uint32_t kb = j * 32;
            uint32_t bv[16][2];
#pragma unroll
            for (int p = 0; p < 8; p++)
                ldsm_x4(bv[2 * p][0], bv[2 * p][1], bv[2 * p + 1][0], bv[2 * p + 1][1],
                        vs_u + v_loff + p * 16 * VTSTR * 2 + kb);
#pragma unroll
            for (int nt = 0; nt < 16; nt++)
                mma_f16(o[nt][0], o[nt][1], o[nt][2], o[nt][3],
                        paf[j][0], paf[j][1], paf[j][2], paf[j][3],
                        bv[nt][0], bv[nt][1]);
        }
        // no trailing barrier: next iteration's top barrier orders stage reuse
    }

    // ---- epilogue ----
#pragma unroll
    for (int hf = 0; hf < 2; hf++) {
        const float inv = 1.0f / l_i[hf];
        const int row = q0 + r0 + q + hf * 8;
        __half* Orow = O + (size_t)row * (NH * HD) + h * HD;
#pragma unroll
        for (int nt = 0; nt < 16; nt++) {
            const int col = nt * 8 + 2 * t;
            *(uint32_t*)(Orow + col) = packh2(o[nt][hf * 2] * inv, o[nt][hf * 2 + 1] * inv);
        }
    }
}

// =================================================================
// launch
// =================================================================
extern "C" void kernel_launch(void* const* d_in, const int* in_sizes, int n_in,
                              void* d_out, int out_size)
{
    const float* hs   = (const float*)d_in[0];
    const float* cosv = (const float*)d_in[1];
    const float* sinv = (const float*)d_in[2];
    const float* wq   = (const float*)d_in[3];
    const float* wk   = (const float*)d_in[4];
    const float* wv   = (const float*)d_in[5];
    const float* wo   = (const float*)d_in[6];
    const float* qw   = (const float*)d_in[7];
    const float* kw   = (const float*)d_in[8];
    float* out = (float*)d_out;

    __half *HSp, *WQp, *WKp, *WVp, *WOp, *Q16p, *K16p, *VTp, *AOp;
    cudaGetSymbolAddress((void**)&HSp,  g_HS16);
    cudaGetSymbolAddress((void**)&WQp,  g_WQ16);
    cudaGetSymbolAddress((void**)&WKp,  g_WK16);
    cudaGetSymbolAddress((void**)&WVp,  g_WV16);
    cudaGetSymbolAddress((void**)&WOp,  g_WO16);
    cudaGetSymbolAddress((void**)&Q16p, g_Q16);
    cudaGetSymbolAddress((void**)&K16p, g_K16);
    cudaGetSymbolAddress((void**)&VTp,  g_VT16);
    cudaGetSymbolAddress((void**)&AOp,  g_AO16);

    cudaFuncSetAttribute(qkv_fused, cudaFuncAttributeMaxDynamicSharedMemorySize, GEMM3_SMEM);
    cudaFuncSetAttribute(gemm_one,  cudaFuncAttributeMaxDynamicSharedMemorySize, GEMM3_SMEM);
    cudaFuncSetAttribute(flash_h,   cudaFuncAttributeMaxDynamicSharedMemorySize, FLASH_SMEM);

    const int n4_hs = SEQ * HID / 4;
    {
        dim3 grid((n4_hs + 255) / 256, 5);
        cvt_h5<<<grid, 256>>>((const float4*)hs, (__half2*)HSp, n4_hs,
                              (const float4*)wq, (__half2*)WQp, NH * HD * HID / 4,
                              (const float4*)wk, (__half2*)WKp, NKV * HD * HID / 4,
                              (const float4*)wv, (__half2*)WVp, NKV * HD * HID / 4,
                              (const float4*)wo, (__half2*)WOp, HID * NH * HD / 4);
    }

    // fused Q/K/V projections (Q,K with RMSNorm+RoPE; V transposed)
    qkv_fused<<<1024, 256, GEMM3_SMEM>>>(HSp, WQp, WKp, WVp, Q16p, K16p, VTp,
                                         qw, kw, cosv, sinv);

    // causal flash attention (GQA)
    flash_h<<<dim3(SEQ / FQ, NH), 256, FLASH_SMEM>>>(Q16p, K16p, VTp, AOp);

    // output projection -> fp32
    gemm_one<<<dim3(HID / 128, SEQ / 128), 256, GEMM3_SMEM>>>(AOp, WOp, out, HID, HID, 0);
}

// round 14
// speedup vs baseline: 1.1342x; 1.1342x over previous
#include <cuda_runtime.h>
#include <cuda_fp16.h>
#include <math.h>
#include <stdint.h>

#define SEQ   4096
#define HID   2048
#define NH    16
#define NKV   8
#define HD    128

// ---------------- scratch ----------------
__device__ __half g_HS16[SEQ * HID];
__device__ __half g_WQ16[NH  * HD * HID];
__device__ __half g_WK16[NKV * HD * HID];
__device__ __half g_WV16[NKV * HD * HID];
__device__ __half g_WO16[HID * NH * HD];
__device__ __half g_Q16 [SEQ * NH  * HD];
__device__ __half g_K16 [SEQ * NKV * HD];
__device__ __half g_VT16[NKV * HD * SEQ];
__device__ __half g_AO16[SEQ * NH  * HD];

#define QSCALE (0.08838834764831845f * 1.4426950408889634f)

// ---------------- PTX helpers ----------------
__device__ __forceinline__ void mma_f16(float& d0, float& d1, float& d2, float& d3,
                                        uint32_t a0, uint32_t a1, uint32_t a2, uint32_t a3,
                                        uint32_t b0, uint32_t b1)
{
    asm volatile(
        "mma.sync.aligned.m16n8k16.row.col.f32.f16.f16.f32 "
        "{%0,%1,%2,%3},{%4,%5,%6,%7},{%8,%9},{%0,%1,%2,%3};\n"
        : "+f"(d0), "+f"(d1), "+f"(d2), "+f"(d3)
        : "r"(a0), "r"(a1), "r"(a2), "r"(a3), "r"(b0), "r"(b1));
}
__device__ __forceinline__ void ldsm_x4(uint32_t& r0, uint32_t& r1,
                                        uint32_t& r2, uint32_t& r3, uint32_t addr)
{
    asm volatile("ldmatrix.sync.aligned.m8n8.x4.shared.b16 {%0,%1,%2,%3}, [%4];"
                 : "=r"(r0), "=r"(r1), "=r"(r2), "=r"(r3) : "r"(addr));
}
__device__ __forceinline__ uint32_t smem_u32(const void* p)
{
    return (uint32_t)__cvta_generic_to_shared(p);
}
__device__ __forceinline__ float ex2f(float x)
{
    float r;
    asm("ex2.approx.ftz.f32 %0, %1;" : "=f"(r) : "f"(x));
    return r;
}
__device__ __forceinline__ uint32_t packh2(float lo, float hi)
{
    __half2 h = __floats2half2_rn(lo, hi);
    return *(uint32_t*)&h;
}
__device__ __forceinline__ void cp_async16(void* smem, const void* gmem)
{
    uint32_t s = smem_u32(smem);
    asm volatile("cp.async.cg.shared.global [%0], [%1], 16;\n" :: "r"(s), "l"(gmem));
}
#define CP_COMMIT()  asm volatile("cp.async.commit_group;\n")
#define CP_WAIT(n)   asm volatile("cp.async.wait_group %0;\n" :: "n"(n))

// =================================================================
// batched fp32 -> fp16 convert (5 arrays, one launch)
// =================================================================
__global__ __launch_bounds__(256) void cvt_h5(
    const float4* s0, __half2* d0, int n0,
    const float4* s1, __half2* d1, int n1,
    const float4* s2, __half2* d2, int n2,
    const float4* s3, __half2* d3, int n3,
    const float4* s4, __half2* d4, int n4)
{
    const float4* src; __half2* dst; int n;
    switch (blockIdx.y) {
        case 0: src = s0; dst = d0; n = n0; break;
        case 1: src = s1; dst = d1; n = n1; break;
        case 2: src = s2; dst = d2; n = n2; break;
        case 3: src = s3; dst = d3; n = n3; break;
        default: src = s4; dst = d4; n = n4; break;
    }
    int i = blockIdx.x * blockDim.x + threadIdx.x;
    if (i < n) {
        float4 v = src[i];
        dst[2 * i]     = __floats2half2_rn(v.x, v.y);
        dst[2 * i + 1] = __floats2half2_rn(v.z, v.w);
    }
}

// =================================================================
// GEMM core (R11 config): CTA 128x128, 256 threads, 8 warps 4x2,
// warp tile 32x64, BK=32, 3-stage cp.async, 1 barrier/ktile.
// mode 0: fp32 C; mode 1: fp16 C; mode 2: fused RMSNorm+RoPE -> fp16.
// =================================================================
#define TAS3 40
#define STG3 (2 * 128 * TAS3)
#define GEMM3_SMEM 73728
#define XS 132

__device__ __forceinline__ void gemm_core(
    const __half* __restrict__ A, const __half* __restrict__ B,
    void* __restrict__ Cv, int N, int K, int mode,
    const float* __restrict__ nw, const float* __restrict__ cosv,
    const float* __restrict__ sinv, float outscale,
    int m0, int n0, __half* sh)
{
    const int tid  = threadIdx.x;
    const int w    = tid >> 5, lane = tid & 31;
    const int wm   = w >> 1,   wn   = w & 1;
    const int q    = lane >> 2, t = lane & 3;

    const uint32_t a_loff = (uint32_t)(((wm * 32 + (lane & 15)) * TAS3 + (lane >> 4) * 8) * 2);
    const uint32_t b_loff = (uint32_t)(((wn * 64 + ((lane >> 4) & 1) * 8 + (lane & 7)) * TAS3) * 2
                                       + ((lane >> 3) & 1) * 16);

    float acc[2][8][4];
#pragma unroll
    for (int mt = 0; mt < 2; mt++)
#pragma unroll
        for (int nt = 0; nt < 8; nt++)
#pragma unroll
            for (int c = 0; c < 4; c++) acc[mt][nt][c] = 0.0f;

    const int T = K / 32;

    auto load_stage = [&](int k0, int st) {
        __half* as = sh + st * STG3;
        __half* bs = as + 128 * TAS3;
#pragma unroll
        for (int it = 0; it < 2; it++) {
            int li  = tid + it * 256;
            int row = li >> 2;
            int c   = (li & 3) * 8;
            cp_async16(as + row * TAS3 + c, A + (size_t)(m0 + row) * K + k0 + c);
            cp_async16(bs + row * TAS3 + c, B + (size_t)(n0 + row) * K + k0 + c);
        }
        CP_COMMIT();
    };

    load_stage(0, 0);
    load_stage(32, 1);

    for (int ti = 0; ti < T; ti++) {
        if (ti == 0) { CP_WAIT(1); }
        __syncthreads();
        if (ti + 2 < T)      { load_stage((ti + 2) * 32, (ti + 2) % 3); CP_WAIT(1); }
        else if (ti + 1 < T) { CP_WAIT(0); }

        const uint32_t as_u = smem_u32(sh + (ti % 3) * STG3);
        const uint32_t bs_u = as_u + 128 * TAS3 * 2;

#pragma unroll
        for (int ks = 0; ks < 2; ks++) {
            const uint32_t kb = ks * 32;
            uint32_t af[2][4], bf[8][2];
            ldsm_x4(af[0][0], af[0][1], af[0][2], af[0][3], as_u + a_loff + kb);
            ldsm_x4(af[1][0], af[1][1], af[1][2], af[1][3],
                    as_u + a_loff + 16 * TAS3 * 2 + kb);
#pragma unroll
            for (int p = 0; p < 4; p++)
                ldsm_x4(bf[2 * p][0], bf[2 * p][1], bf[2 * p + 1][0], bf[2 * p + 1][1],
                        bs_u + b_loff + p * 16 * TAS3 * 2 + kb);
#pragma unroll
            for (int mt = 0; mt < 2; mt++)
#pragma unroll
                for (int nt = 0; nt < 8; nt++)
                    mma_f16(acc[mt][nt][0], acc[mt][nt][1], acc[mt][nt][2], acc[mt][nt][3],
                            af[mt][0], af[mt][1], af[mt][2], af[mt][3],
                            bf[nt][0], bf[nt][1]);
        }
    }

    if (mode == 0) {
        float* C = (float*)Cv;
#pragma unroll
        for (int mt = 0; mt < 2; mt++) {
            const int row = m0 + wm * 32 + mt * 16 + q;
#pragma unroll
            for (int nt = 0; nt < 8; nt++) {
                const int col = n0 + wn * 64 + nt * 8 + 2 * t;
                *(float2*)(C + (size_t)row * N + col)       = make_float2(acc[mt][nt][0], acc[mt][nt][1]);
                *(float2*)(C + (size_t)(row + 8) * N + col) = make_float2(acc[mt][nt][2], acc[mt][nt][3]);
            }
        }
    } else if (mode == 1) {
        __half* C = (__half*)Cv;
#pragma unroll
        for (int mt = 0; mt < 2; mt++) {
            const int row = m0 + wm * 32 + mt * 16 + q;
#pragma unroll
            for (int nt = 0; nt < 8; nt++) {
                const int col = n0 + wn * 64 + nt * 8 + 2 * t;
                *(uint32_t*)(C + (size_t)row * N + col)       = packh2(acc[mt][nt][0], acc[mt][nt][1]);
                *(uint32_t*)(C + (size_t)(row + 8) * N + col) = packh2(acc[mt][nt][2], acc[mt][nt][3]);
            }
        }
    } else {
        __syncthreads();
        float* red  = (float*)sh;
        float* xbuf = (float*)sh + 256;

#pragma unroll
        for (int mt = 0; mt < 2; mt++)
#pragma unroll
            for (int hf = 0; hf < 2; hf++) {
                float ss = 0.0f;
#pragma unroll
                for (int nt = 0; nt < 8; nt++) {
                    float a0 = acc[mt][nt][hf * 2], a1 = acc[mt][nt][hf * 2 + 1];
                    ss += a0 * a0 + a1 * a1;
                }
                ss += __shfl_xor_sync(0xffffffffu, ss, 1);
                ss += __shfl_xor_sync(0xffffffffu, ss, 2);
                if (t == 0) red[(wm * 32 + mt * 16 + q + hf * 8) * 2 + wn] = ss;
            }
        __syncthreads();

#pragma unroll
        for (int mt = 0; mt < 2; mt++)
#pragma unroll
            for (int hf = 0; hf < 2; hf++) {
                const int row = wm * 32 + mt * 16 + q + hf * 8;
                const float tot = red[row * 2] + red[row * 2 + 1];
                const float rms = rsqrtf(tot * (1.0f / HD) + 1e-6f);
#pragma unroll
                for (int nt = 0; nt < 8; nt++) {
                    const int col = wn * 64 + nt * 8 + 2 * t;
                    xbuf[row * XS + col]     = acc[mt][nt][hf * 2]     * rms * nw[col];
                    xbuf[row * XS + col + 1] = acc[mt][nt][hf * 2 + 1] * rms * nw[col + 1];
                }
            }
        __syncthreads();

        __half* C = (__half*)Cv;
        const float sgn = (wn == 0) ? -1.0f : 1.0f;
#pragma unroll
        for (int mt = 0; mt < 2; mt++)
#pragma unroll
            for (int hf = 0; hf < 2; hf++) {
                const int row = wm * 32 + mt * 16 + q + hf * 8;
                const int s   = m0 + row;
                __half* Orow  = C + (size_t)s * N + n0;
#pragma unroll
                for (int nt = 0; nt < 8; nt++) {
                    const int col = wn * 64 + nt * 8 + 2 * t;
                    float x0 = xbuf[row * XS + col];
                    float x1 = xbuf[row * XS + col + 1];
                    float p0 = xbuf[row * XS + (col ^ 64)];
                    float p1 = xbuf[row * XS + (col ^ 64) + 1];
                    float2 cs = *(const float2*)(cosv + (size_t)s * HD + col);
                    float2 sn = *(const float2*)(sinv + (size_t)s * HD + col);
                    float r0 = (x0 * cs.x + sgn * p0 * sn.x) * outscale;
                    float r1 = (x1 * cs.y + sgn * p1 * sn.y) * outscale;
                    *(uint32_t*)(Orow + col) = packh2(r0, r1);
                }
            }
    }
}

__global__ __launch_bounds__(256, 2) void qkv_fused(
    const __half* __restrict__ HS, const __half* __restrict__ WQ,
    const __half* __restrict__ WK, const __half* __restrict__ WV,
    __half* __restrict__ Q16, __half* __restrict__ K16, __half* __restrict__ VT,
    const float* __restrict__ qw, const float* __restrict__ kw,
    const float* __restrict__ cosv, const float* __restrict__ sinv)
{
    extern __shared__ __half sh[];
    const int bid = blockIdx.x;
    const __half *A, *B; void* C; int N, mode, m0, n0;
    const float* nwp = nullptr; float osc = 0.0f;
    if (bid < 512) {
        A = HS; B = WQ; C = Q16; N = 2048; mode = 2; nwp = qw; osc = QSCALE;
        n0 = (bid & 15) * 128; m0 = (bid >> 4) * 128;
    } else if (bid < 768) {
        int r = bid - 512;
        A = HS; B = WK; C = K16; N = 1024; mode = 2; nwp = kw; osc = 1.0f;
        n0 = (r & 7) * 128; m0 = (r >> 3) * 128;
    } else {
        int r = bid - 768;
        A = WV; B = HS; C = VT; N = 4096; mode = 1;
        n0 = (r & 31) * 128; m0 = (r >> 5) * 128;
    }
    gemm_core(A, B, C, N, HID, mode, nwp, cosv, sinv, osc, m0, n0, sh);
}

__global__ __launch_bounds__(256, 2) void gemm_one(
    const __half* __restrict__ A, const __half* __restrict__ B,
    void* __restrict__ Cv, int N, int K, int mode)
{
    extern __shared__ __half sh[];
    gemm_core(A, B, Cv, N, K, mode, nullptr, nullptr, nullptr, 0.0f,
              blockIdx.y * 128, blockIdx.x * 128, sh);
}

// =================================================================
// Causal flash attention — 2-stage R11 core, PAIRED q-tiles per CTA:
// CTA c handles tiles {31-pair, pair} of head c>>4 -> uniform 66 ktiles.
// =================================================================
#define FQ   128
#define FK   64
#define KSTR 136
#define VTSTR 72
#define QSTR 136
#define KVSTG (FK * KSTR + FQ * VTSTR)
#define FLASH_SMEM (2 * KVSTG * 2)
#define NQT  (SEQ / FQ)     // 32 q-tiles per head

__global__ __launch_bounds__(256) void flash_h(const __half* __restrict__ Q,
                                               const __half* __restrict__ K,
                                               const __half* __restrict__ VT,
                                               __half* __restrict__ O)
{
    extern __shared__ __half sh[];

    const int tid  = threadIdx.x;
    const int w    = tid >> 5, lane = tid & 31;
    const int q    = lane >> 2, t = lane & 3;
    const int h    = blockIdx.x >> 4;       // 16 pairs per head
    const int pair = blockIdx.x & 15;
    const int kvh  = h >> 1;
    const int r0   = w * 16;

    const __half* Qb  = Q  + (size_t)h * HD;
    const __half* Kb  = K  + (size_t)kvh * HD;
    const __half* VTb = VT + (size_t)(kvh * HD) * SEQ;

    const uint32_t k_loff = (uint32_t)(((((lane >> 4) & 1) * 8 + (lane & 7)) * KSTR) * 2
                                       + ((lane >> 3) & 1) * 16);
    const uint32_t v_loff = (uint32_t)(((((lane >> 4) & 1) * 8 + (lane & 7)) * VTSTR) * 2
                                       + ((lane >> 3) & 1) * 16);

    auto prefetch = [&](int kt, int st) {
        __half* Ks = sh + st * KVSTG;
        __half* Vs = Ks + FK * KSTR;
        const int k0 = kt * FK;
#pragma unroll
        for (int it = 0; it < 4; it++) {
            int li = tid + it * 256;
            int r  = li >> 4;
            int c  = (li & 15) * 8;
            cp_async16(Ks + r * KSTR + c, Kb + (size_t)(k0 + r) * (NKV * HD) + c);
        }
#pragma unroll
        for (int it = 0; it < 4; it++) {
            int li = tid + it * 256;
            int r  = li >> 3;
            int c  = (li & 7) * 8;
            cp_async16(Vs + r * VTSTR + c, VTb + (size_t)r * SEQ + k0 + c);
        }
        CP_COMMIT();
    };

    // two jobs: heavy tile first, then its light complement
#pragma unroll 1
    for (int jid = 0; jid < 2; jid++) {
        const int qt = (jid == 0) ? (NQT - 1 - pair) : pair;
        const int q0 = qt * FQ;

        // ---- stage Q into stage-0 area, extract fragments ----
        uint32_t qf[8][4];
        {
            __half* Qs = sh;
#pragma unroll
            for (int it = 0; it < 8; it++) {
                int li = tid + it * 256;
                int r  = li >> 4;
                int c  = (li & 15) * 8;
                *(float4*)(Qs + r * QSTR + c) =
                    *(const float4*)(Qb + (size_t)(q0 + r) * (NH * HD) + c);
            }
            __syncthreads();
            const uint32_t qs_u = smem_u32(Qs);
            const uint32_t q_loff = (uint32_t)(((r0 + (lane & 15)) * QSTR + (lane >> 4) * 8) * 2);
#pragma unroll
            for (int ks = 0; ks < 8; ks++)
                ldsm_x4(qf[ks][0], qf[ks][1], qf[ks][2], qf[ks][3], qs_u + q_loff + ks * 32);
            __syncthreads();
        }

        float o[16][4];
        float m_i[2], l_i[2];
#pragma unroll
        for (int hf = 0; hf < 2; hf++) { m_i[hf] = -1e30f; l_i[hf] = 0.0f; }
#pragma unroll
        for (int nt = 0; nt < 16; nt++)
#pragma unroll
            for (int c = 0; c < 4; c++) o[nt][c] = 0.0f;

        const int ktiles = q0 / FK + 2;

        prefetch(0, 0);

        for (int kt = 0; kt < ktiles; kt++) {
            const int st = kt & 1;
            const int k0 = kt * FK;

            if (kt + 1 < ktiles) { prefetch(kt + 1, st ^ 1); CP_WAIT(1); }
            else                 { CP_WAIT(0); }
            __syncthreads();

            const uint32_t ks_u = smem_u32(sh + st * KVSTG);
            const uint32_t vs_u = ks_u + FK * KSTR * 2;

            float s[8][4];
#pragma unroll
            for (int nt = 0; nt < 8; nt++)
#pragma unroll
                for (int c = 0; c < 4; c++) s[nt][c] = 0.0f;

#pragma unroll
            for (int ks = 0; ks < 8; ks++) {
                const uint32_t kb = ks * 32;
                uint32_t bf[8][2];
#pragma unroll
                for (int p = 0; p < 4; p++)
                    ldsm_x4(bf[2 * p][0], bf[2 * p][1], bf[2 * p + 1][0], bf[2 * p + 1][1],
                            ks_u + k_loff + p * 16 * KSTR * 2 + kb);
#pragma unroll
                for (int nt = 0; nt < 8; nt++)
                    mma_f16(s[nt][0], s[nt][1], s[nt][2], s[nt][3],
                            qf[ks][0], qf[ks][1], qf[ks][2], qf[ks][3],
                            bf[nt][0], bf[nt][1]);
            }

            if (k0 + FK - 1 > q0) {
#pragma unroll
                for (int hf = 0; hf < 2; hf++) {
                    const int row = q0 + r0 + q + hf * 8;
#pragma unroll
                    for (int nt = 0; nt < 8; nt++) {
                        const int col = k0 + nt * 8 + 2 * t;
                        if (col     > row) s[nt][hf * 2]     = -1e30f;
                        if (col + 1 > row) s[nt][hf * 2 + 1] = -1e30f;
                    }
                }
            }

#pragma unroll
            for (int hf = 0; hf < 2; hf++) {
                float rm = -1e30f;
#pragma unroll
                for (int nt = 0; nt < 8; nt++)
                    rm = fmaxf(rm, fmaxf(s[nt][hf * 2], s[nt][hf * 2 + 1]));
                rm = fmaxf(rm, __shfl_xor_sync(0xffffffffu, rm, 1));
                rm = fmaxf(rm, __shfl_xor_sync(0xffffffffu, rm, 2));

                const float mnew  = fmaxf(m_i[hf], rm);
                const float alpha = ex2f(m_i[hf] - mnew);
                float rs = 0.0f;
#pragma unroll
                for (int nt = 0; nt < 8; nt++) {
                    float p0 = ex2f(s[nt][hf * 2]     - mnew);
                    float p1 = ex2f(s[nt][hf * 2 + 1] - mnew);
                    rs += p0 + p1;
                    s[nt][hf * 2]     = p0;
                    s[nt][hf * 2 + 1] = p1;
                }
                rs += __shfl_xor_sync(0xffffffffu, rs, 1);
                rs += __shfl_xor_sync(0xffffffffu, rs, 2);

                l_i[hf] = l_i[hf] * alpha + rs;
                m_i[hf] = mnew;

                if (__any_sync(0xffffffffu, alpha != 1.0f)) {
#pragma unroll
                    for (int nt = 0; nt < 16; nt++) {
                        o[nt][hf * 2]     *= alpha;
                        o[nt][hf * 2 + 1] *= alpha;
                    }
                }
            }

            uint32_t paf[4][4];
#pragma unroll
            for (int j = 0; j < 4; j++) {
                paf[j][0] = packh2(s[2 * j][0],     s[2 * j][1]);
                paf[j][1] = packh2(s[2 * j][2],     s[2 * j][3]);
                paf[j][2] = packh2(s[2 * j + 1][0], s[2 * j + 1][1]);
                paf[j][3] = packh2(s[2 * j + 1][2], s[2 * j + 1][3]);
            }

#pragma unroll
            for (int j = 0; j < 4; j++) {
                const uint32_t kb = j * 32;
                uint32_t bv[16][2];
#pragma unroll
                for (int p = 0; p < 8; p++)
                    ldsm_x4(bv[2 * p][0], bv[2 * p][1], bv[2 * p + 1][0], bv[2 * p + 1][1],
                            vs_u + v_loff + p * 16 * VTSTR * 2 + kb);
#pragma unroll
                for (int nt = 0; nt < 16; nt++)
                    mma_f16(o[nt][0], o[nt][1], o[nt][2], o[nt][3],
                            paf[j][0], paf[j][1], paf[j][2], paf[j][3],
                            bv[nt][0], bv[nt][1]);
            }
            __syncthreads();   // protects stage reuse AND next job's Q staging
        }

        // ---- epilogue for this job ----
#pragma unroll
        for (int hf = 0; hf < 2; hf++) {
            const float inv = 1.0f / l_i[hf];
            const int row = q0 + r0 + q + hf * 8;
            __half* Orow = O + (size_t)row * (NH * HD) + h * HD;
#pragma unroll
            for (int nt = 0; nt < 16; nt++) {
                const int col = nt * 8 + 2 * t;
                *(uint32_t*)(Orow + col) = packh2(o[nt][hf * 2] * inv, o[nt][hf * 2 + 1] * inv);
            }
        }
    }
}

// =================================================================
// launch
// =================================================================
extern "C" void kernel_launch(void* const* d_in, const int* in_sizes, int n_in,
                              void* d_out, int out_size)
{
    const float* hs   = (const float*)d_in[0];
    const float* cosv = (const float*)d_in[1];
    const float* sinv = (const float*)d_in[2];
    const float* wq   = (const float*)d_in[3];
    const float* wk   = (const float*)d_in[4];
    const float* wv   = (const float*)d_in[5];
    const float* wo   = (const float*)d_in[6];
    const float* qw   = (const float*)d_in[7];
    const float* kw   = (const float*)d_in[8];
    float* out = (float*)d_out;

    __half *HSp, *WQp, *WKp, *WVp, *WOp, *Q16p, *K16p, *VTp, *AOp;
    cudaGetSymbolAddress((void**)&HSp,  g_HS16);
    cudaGetSymbolAddress((void**)&WQp,  g_WQ16);
    cudaGetSymbolAddress((void**)&WKp,  g_WK16);
    cudaGetSymbolAddress((void**)&WVp,  g_WV16);
    cudaGetSymbolAddress((void**)&WOp,  g_WO16);
    cudaGetSymbolAddress((void**)&Q16p, g_Q16);
    cudaGetSymbolAddress((void**)&K16p, g_K16);
    cudaGetSymbolAddress((void**)&VTp,  g_VT16);
    cudaGetSymbolAddress((void**)&AOp,  g_AO16);

    cudaFuncSetAttribute(qkv_fused, cudaFuncAttributeMaxDynamicSharedMemorySize, GEMM3_SMEM);
    cudaFuncSetAttribute(gemm_one,  cudaFuncAttributeMaxDynamicSharedMemorySize, GEMM3_SMEM);
    cudaFuncSetAttribute(flash_h,   cudaFuncAttributeMaxDynamicSharedMemorySize, FLASH_SMEM);

    const int n4_hs = SEQ * HID / 4;
    {
        dim3 grid((n4_hs + 255) / 256, 5);
        cvt_h5<<<grid, 256>>>((const float4*)hs, (__half2*)HSp, n4_hs,
                              (const float4*)wq, (__half2*)WQp, NH * HD * HID / 4,
                              (const float4*)wk, (__half2*)WKp, NKV * HD * HID / 4,
                              (const float4*)wv, (__half2*)WVp, NKV * HD * HID / 4,
                              (const float4*)wo, (__half2*)WOp, HID * NH * HD / 4);
    }

    // fused Q/K/V projections (Q,K with RMSNorm+RoPE; V transposed)
    qkv_fused<<<1024, 256, GEMM3_SMEM>>>(HSp, WQp, WKp, WVp, Q16p, K16p, VTp,
                                         qw, kw, cosv, sinv);

    // causal flash attention (GQA), paired q-tiles -> uniform CTA cost
    flash_h<<<NH * (NQT / 2), 256, FLASH_SMEM>>>(Q16p, K16p, VTp, AOp);

    // output projection -> fp32
    gemm_one<<<dim3(HID / 128, SEQ / 128), 256, GEMM3_SMEM>>>(AOp, WOp, out, HID, HID, 0);
}